// round 11
// baseline (speedup 1.0000x reference)
#include <cuda_runtime.h>
#include <cuda_bf16.h>
#include <math.h>
#include <stdint.h>

#define D_MODEL 1024
#define NUM_HEADS 16
#define DK 64
#define BATCH 2
#define SEQ 2048
#define MROWS (BATCH * SEQ)   // 4096

#define LOG2E 1.4426950408889634f

// ---------------- scratch (static device globals; no allocations) ----------
__device__ float g_qh[BATCH * NUM_HEADS * SEQ * DK];   // [B,H,S,64]
__device__ float g_kh[BATCH * NUM_HEADS * SEQ * DK];
__device__ float g_vh[BATCH * NUM_HEADS * SEQ * DK];
__device__ float g_ctx[MROWS * D_MODEL];               // [B*S, 1024]

// ---------------------------------------------------------------------------
// helpers
// ---------------------------------------------------------------------------
__device__ __forceinline__ uint32_t f2tf32(float x) {
    uint32_t u;
    asm("cvt.rna.tf32.f32 %0, %1;" : "=r"(u) : "f"(x));
    return u;
}

__device__ __forceinline__ float4 cvt4(float4 v) {
    v.x = __uint_as_float(f2tf32(v.x));
    v.y = __uint_as_float(f2tf32(v.y));
    v.z = __uint_as_float(f2tf32(v.z));
    v.w = __uint_as_float(f2tf32(v.w));
    return v;
}

// D += A(16x8) * B(8x8), tf32 inputs, fp32 accum
__device__ __forceinline__ void mma_tf32(float* c, const uint32_t* a, const uint32_t* b) {
    asm volatile(
        "mma.sync.aligned.m16n8k8.row.col.f32.tf32.tf32.f32 "
        "{%0,%1,%2,%3},{%4,%5,%6,%7},{%8,%9},{%0,%1,%2,%3};"
        : "+f"(c[0]), "+f"(c[1]), "+f"(c[2]), "+f"(c[3])
        : "r"(a[0]), "r"(a[1]), "r"(a[2]), "r"(a[3]), "r"(b[0]), "r"(b[1]));
}

// fast exp2 on the FMA pipe: x <= 0 (can be -inf). rel err ~1e-7.
__device__ __forceinline__ float fexp2(float x) {
    x = fmaxf(x, -126.0f);
    float t = x + 12582912.0f;                 // 1.5 * 2^23 (round-to-nearest int)
    int  ei = __float_as_int(t) - 0x4B400000;  // integer part
    float f = x - (t - 12582912.0f);           // frac in [-0.5, 0.5]
    float p = 1.5403530e-4f;
    p = fmaf(p, f, 1.3333558e-3f);
    p = fmaf(p, f, 9.6181291e-3f);
    p = fmaf(p, f, 5.5504109e-2f);
    p = fmaf(p, f, 2.4022650e-1f);
    p = fmaf(p, f, 6.9314718e-1f);
    p = fmaf(p, f, 1.0f);
    return p * __int_as_float((ei + 127) << 23);
}

// ---------------------------------------------------------------------------
// tf32 tensor-core GEMM: out[m,n] = (sum_k A[m,k]*W[n,k] + bias[n]) * scale
// A: [4096,1024], W: [1024,1024] row-major (row n = output feature).
// BM=BN=128, BK=16, 256 threads = 8 warps (2M x 4N), warp tile 64x32.
// ---------------------------------------------------------------------------
template <bool HEAD_LAYOUT>
__global__ __launch_bounds__(256)
void gemm_tf32_kernel(const float* __restrict__ A,
                      const float* __restrict__ W,
                      const float* __restrict__ bias,
                      float* __restrict__ out,
                      float scale)
{
    __shared__ float As[128 * 20];   // [m][k], pad to 20 -> conflict-free frags
    __shared__ float Ws[128 * 20];   // [n][k]

    const int tid  = threadIdx.x;
    const int lane = tid & 31;
    const int warp = tid >> 5;
    const int wm = warp & 1;         // 0..1
    const int wn = warp >> 1;        // 0..3
    const int g  = lane >> 2;        // 0..7
    const int c  = lane & 3;         // 0..3
    const int blockM = blockIdx.y * 128;
    const int blockN = blockIdx.x * 128;

    float acc[4][4][4];
#pragma unroll
    for (int mt = 0; mt < 4; mt++)
#pragma unroll
        for (int nt = 0; nt < 4; nt++)
#pragma unroll
            for (int r = 0; r < 4; r++) acc[mt][nt][r] = 0.f;

    for (int kt = 0; kt < D_MODEL / 16; kt++) {
        const int k0 = kt * 16;
#pragma unroll
        for (int it = 0; it < 2; it++) {
            int idx = tid + it * 256;       // 0..511
            int row = idx >> 2;             // 0..127
            int c4  = (idx & 3) * 4;        // 0,4,8,12
            float4 av = *reinterpret_cast<const float4*>(
                A + (size_t)(blockM + row) * D_MODEL + k0 + c4);
            *reinterpret_cast<float4*>(&As[row * 20 + c4]) = cvt4(av);
            float4 wv = *reinterpret_cast<const float4*>(
                W + (size_t)(blockN + row) * D_MODEL + k0 + c4);
            *reinterpret_cast<float4*>(&Ws[row * 20 + c4]) = cvt4(wv);
        }
        __syncthreads();

#pragma unroll
        for (int ks = 0; ks < 2; ks++) {
            uint32_t af[4][4], bf[4][2];
#pragma unroll
            for (int mt = 0; mt < 4; mt++) {
                const uint32_t* p = reinterpret_cast<const uint32_t*>(As)
                                  + (wm * 64 + mt * 16 + g) * 20 + ks * 8 + c;
                af[mt][0] = p[0];
                af[mt][1] = p[8 * 20];
                af[mt][2] = p[4];
                af[mt][3] = p[8 * 20 + 4];
            }
#pragma unroll
            for (int nt = 0; nt < 4; nt++) {
                const uint32_t* p = reinterpret_cast<const uint32_t*>(Ws)
                                  + (wn * 32 + nt * 8 + g) * 20 + ks * 8 + c;
                bf[nt][0] = p[0];
                bf[nt][1] = p[4];
            }
#pragma unroll
            for (int mt = 0; mt < 4; mt++)
#pragma unroll
                for (int nt = 0; nt < 4; nt++)
                    mma_tf32(acc[mt][nt], af[mt], bf[nt]);
        }
        __syncthreads();
    }

    // epilogue: rows g/g+8, col pairs 2c,2c+1
#pragma unroll
    for (int mt = 0; mt < 4; mt++) {
#pragma unroll
        for (int half = 0; half < 2; half++) {
            const int m = blockM + wm * 64 + mt * 16 + g + half * 8;
#pragma unroll
            for (int nt = 0; nt < 4; nt++) {
                const int n = blockN + wn * 32 + nt * 8 + 2 * c;
                float v0 = (acc[mt][nt][half * 2 + 0] + bias[n])     * scale;
                float v1 = (acc[mt][nt][half * 2 + 1] + bias[n + 1]) * scale;
                if (HEAD_LAYOUT) {
                    const int b = m >> 11;
                    const int s = m & 2047;
                    const int h = n >> 6;
                    const int d = n & 63;
                    float2* dst = reinterpret_cast<float2*>(
                        out + (((size_t)(b * NUM_HEADS + h) * SEQ + s) * DK) + d);
                    *dst = make_float2(v0, v1);
                } else {
                    float2* dst = reinterpret_cast<float2*>(
                        out + (size_t)m * D_MODEL + n);
                    *dst = make_float2(v0, v1);
                }
            }
        }
    }
}

// ---------------------------------------------------------------------------
// Flash attention with tf32 mma.sync. 128 q-rows per CTA, 8 warps x 16 rows.
// 64-key tiles. Q fragments live in registers for the whole loop.
// smem: Ks[64][72], Vs[64][72], Ps[128][68], maskAdd[64]  (~72 KB dynamic)
// ---------------------------------------------------------------------------
__global__ __launch_bounds__(256)
void flash_attn_tf32_kernel(const float* __restrict__ qh,
                            const float* __restrict__ kh,
                            const float* __restrict__ vh,
                            const int*   __restrict__ mask,
                            float* __restrict__ ctx)
{
    extern __shared__ float smem[];
    float* Ks = smem;                       // [64][72]
    float* Vs = Ks + 64 * 72;               // [64][72]
    float* Ps = Vs + 64 * 72;               // [128][68]
    float* mAdd = Ps + 128 * 68;            // [64]

    const int tid  = threadIdx.x;
    const int lane = tid & 31;
    const int warp = tid >> 5;              // 0..7
    const int g = lane >> 2;                // 0..7
    const int c = lane & 3;                 // 0..3
    const int b = blockIdx.z;
    const int h = blockIdx.y;
    const int q0 = blockIdx.x * 128;
    const int wrow = warp * 16;

    const float* qptr = qh + ((size_t)(b * NUM_HEADS + h) * SEQ + q0 + wrow) * DK;
    const float* kbase = kh + (size_t)(b * NUM_HEADS + h) * SEQ * DK;
    const float* vbase = vh + (size_t)(b * NUM_HEADS + h) * SEQ * DK;

    // Q fragments (A of m16n8k8): 8 k-steps x 4 regs
    uint32_t qa[8][4];
#pragma unroll
    for (int ks = 0; ks < 8; ks++) {
        qa[ks][0] = f2tf32(qptr[(g)     * DK + ks * 8 + c]);
        qa[ks][1] = f2tf32(qptr[(g + 8) * DK + ks * 8 + c]);
        qa[ks][2] = f2tf32(qptr[(g)     * DK + ks * 8 + c + 4]);
        qa[ks][3] = f2tf32(qptr[(g + 8) * DK + ks * 8 + c + 4]);
    }

    float m0 = -INFINITY, m1 = -INFINITY;
    float l0 = 0.f, l1 = 0.f;
    float o[8][4];
#pragma unroll
    for (int dt = 0; dt < 8; dt++)
#pragma unroll
        for (int r = 0; r < 4; r++) o[dt][r] = 0.f;

    for (int kt = 0; kt < SEQ / 64; kt++) {
        __syncthreads();   // protect smem from previous iteration's readers
        const float* kp = kbase + (size_t)kt * 64 * DK;
        const float* vp = vbase + (size_t)kt * 64 * DK;
#pragma unroll
        for (int it = 0; it < 4; it++) {
            int idx = tid + it * 256;        // 0..1023
            int r  = idx >> 4;               // 0..63
            int c4 = (idx & 15) * 4;         // 0..60
            float4 kv = *reinterpret_cast<const float4*>(kp + r * DK + c4);
            *reinterpret_cast<float4*>(&Ks[r * 72 + c4]) = cvt4(kv);
            float4 vv = *reinterpret_cast<const float4*>(vp + r * DK + c4);
            *reinterpret_cast<float4*>(&Vs[r * 72 + c4]) = cvt4(vv);
        }
        if (tid < 64) mAdd[tid] = (mask[b * SEQ + kt * 64 + tid] != 0) ? 0.f : -1e9f;
        __syncthreads();

        // ---- scores: S(16 x 64) = Q K^T ----
        float sc[8][4];
#pragma unroll
        for (int nt = 0; nt < 8; nt++) {
#pragma unroll
            for (int r = 0; r < 4; r++) sc[nt][r] = 0.f;
#pragma unroll
            for (int ks = 0; ks < 8; ks++) {
                uint32_t bf[2];
                const uint32_t* p = reinterpret_cast<const uint32_t*>(Ks)
                                  + (nt * 8 + g) * 72 + ks * 8 + c;
                bf[0] = p[0];
                bf[1] = p[4];
                mma_tf32(sc[nt], qa[ks], bf);
            }
            float ma0 = mAdd[nt * 8 + 2 * c];
            float ma1 = mAdd[nt * 8 + 2 * c + 1];
            sc[nt][0] += ma0; sc[nt][1] += ma1;
            sc[nt][2] += ma0; sc[nt][3] += ma1;
        }

        // ---- online softmax in C-register layout ----
        float tm0 = -INFINITY, tm1 = -INFINITY;
#pragma unroll
        for (int nt = 0; nt < 8; nt++) {
            tm0 = fmaxf(tm0, fmaxf(sc[nt][0], sc[nt][1]));
            tm1 = fmaxf(tm1, fmaxf(sc[nt][2], sc[nt][3]));
        }
        tm0 = fmaxf(tm0, __shfl_xor_sync(0xffffffffu, tm0, 1));
        tm0 = fmaxf(tm0, __shfl_xor_sync(0xffffffffu, tm0, 2));
        tm1 = fmaxf(tm1, __shfl_xor_sync(0xffffffffu, tm1, 1));
        tm1 = fmaxf(tm1, __shfl_xor_sync(0xffffffffu, tm1, 2));

        const float mn0 = fmaxf(m0, tm0);
        const float mn1 = fmaxf(m1, tm1);
        const float alpha0 = fexp2((m0 - mn0) * LOG2E);
        const float alpha1 = fexp2((m1 - mn1) * LOG2E);
        const float mn2_0 = mn0 * LOG2E;
        const float mn2_1 = mn1 * LOG2E;

        float ls0 = 0.f, ls1 = 0.f;
#pragma unroll
        for (int nt = 0; nt < 8; nt++) {
            float p0 = fexp2(fmaf(sc[nt][0], LOG2E, -mn2_0));
            float p1 = fexp2(fmaf(sc[nt][1], LOG2E, -mn2_0));
            float p2 = fexp2(fmaf(sc[nt][2], LOG2E, -mn2_1));
            float p3 = fexp2(fmaf(sc[nt][3], LOG2E, -mn2_1));
            p0 = __uint_as_float(f2tf32(p0));
            p1 = __uint_as_float(f2tf32(p1));
            p2 = __uint_as_float(f2tf32(p2));
            p3 = __uint_as_float(f2tf32(p3));
            ls0 += p0 + p1;
            ls1 += p2 + p3;
            *reinterpret_cast<float2*>(&Ps[(wrow + g)     * 68 + nt * 8 + 2 * c]) = make_float2(p0, p1);
            *reinterpret_cast<float2*>(&Ps[(wrow + g + 8) * 68 + nt * 8 + 2 * c]) = make_float2(p2, p3);
        }
        ls0 += __shfl_xor_sync(0xffffffffu, ls0, 1);
        ls0 += __shfl_xor_sync(0xffffffffu, ls0, 2);
        ls1 += __shfl_xor_sync(0xffffffffu, ls1, 1);
        ls1 += __shfl_xor_sync(0xffffffffu, ls1, 2);
        l0 = l0 * alpha0 + ls0;
        l1 = l1 * alpha1 + ls1;
        m0 = mn0;
        m1 = mn1;

#pragma unroll
        for (int dt = 0; dt < 8; dt++) {
            o[dt][0] *= alpha0; o[dt][1] *= alpha0;
            o[dt][2] *= alpha1; o[dt][3] *= alpha1;
        }
        __syncwarp();   // P visible within warp

        // ---- O += P * V ----
#pragma unroll
        for (int ks = 0; ks < 8; ks++) {
            uint32_t pa[4];
            const uint32_t* p = reinterpret_cast<const uint32_t*>(Ps)
                              + (wrow + g) * 68 + ks * 8 + c;
            pa[0] = p[0];
            pa[1] = p[8 * 68];
            pa[2] = p[4];
            pa[3] = p[8 * 68 + 4];
#pragma unroll
            for (int dt = 0; dt < 8; dt++) {
                uint32_t bf[2];
                const uint32_t* q = reinterpret_cast<const uint32_t*>(Vs)
                                  + (ks * 8 + c) * 72 + dt * 8 + g;
                bf[0] = q[0];
                bf[1] = q[4 * 72];
                mma_tf32(o[dt], pa, bf);
            }
        }
    }

    // ---- normalize + write ctx[B*S, 1024] ----
    const float r0 = 1.0f / l0;
    const float r1 = 1.0f / l1;
    float* out0 = ctx + ((size_t)(b * SEQ + q0 + wrow + g)     * D_MODEL) + h * DK;
    float* out1 = ctx + ((size_t)(b * SEQ + q0 + wrow + g + 8) * D_MODEL) + h * DK;
#pragma unroll
    for (int dt = 0; dt < 8; dt++) {
        const int col = dt * 8 + 2 * c;
        *reinterpret_cast<float2*>(out0 + col) = make_float2(o[dt][0] * r0, o[dt][1] * r0);
        *reinterpret_cast<float2*>(out1 + col) = make_float2(o[dt][2] * r1, o[dt][3] * r1);
    }
}

// ---------------------------------------------------------------------------
extern "C" void kernel_launch(void* const* d_in, const int* in_sizes, int n_in,
                              void* d_out, int out_size)
{
    const float* q    = (const float*)d_in[0];
    const float* k    = (const float*)d_in[1];
    const float* v    = (const float*)d_in[2];
    const int*   mask = (const int*)  d_in[3];
    const float* Wq   = (const float*)d_in[4];
    const float* bq   = (const float*)d_in[5];
    const float* Wk   = (const float*)d_in[6];
    const float* bk   = (const float*)d_in[7];
    const float* Wv   = (const float*)d_in[8];
    const float* bv   = (const float*)d_in[9];
    const float* Wo   = (const float*)d_in[10];
    const float* bo   = (const float*)d_in[11];
    float* out = (float*)d_out;

    float *qh, *kh, *vh, *ctx;
    cudaGetSymbolAddress((void**)&qh,  g_qh);
    cudaGetSymbolAddress((void**)&kh,  g_kh);
    cudaGetSymbolAddress((void**)&vh,  g_vh);
    cudaGetSymbolAddress((void**)&ctx, g_ctx);

    dim3 gemm_grid(D_MODEL / 128, MROWS / 128);   // (8, 32)
    const float qscale = 0.125f;                  // 1/sqrt(64)

    gemm_tf32_kernel<true><<<gemm_grid, 256>>>(q, Wq, bq, qh, qscale);
    gemm_tf32_kernel<true><<<gemm_grid, 256>>>(k, Wk, bk, kh, 1.0f);
    gemm_tf32_kernel<true><<<gemm_grid, 256>>>(v, Wv, bv, vh, 1.0f);

    size_t smem_bytes = (64 * 72 * 2 + 128 * 68 + 64) * sizeof(float);
    static bool attr_set = false;
    if (!attr_set) {
        cudaFuncSetAttribute(flash_attn_tf32_kernel,
                             cudaFuncAttributeMaxDynamicSharedMemorySize,
                             (int)smem_bytes);
        attr_set = true;
    }
    dim3 attn_grid(SEQ / 128, NUM_HEADS, BATCH);  // (16,16,2)
    flash_attn_tf32_kernel<<<attn_grid, 256, smem_bytes>>>(qh, kh, vh, mask, ctx);

    gemm_tf32_kernel<false><<<gemm_grid, 256>>>(ctx, Wo, bo, out, 1.0f);
}

// round 12
// speedup vs baseline: 1.0006x; 1.0006x over previous
#include <cuda_runtime.h>
#include <cuda_bf16.h>
#include <math.h>
#include <stdint.h>

#define D_MODEL 1024
#define NUM_HEADS 16
#define DK 64
#define BATCH 2
#define SEQ 2048
#define MROWS (BATCH * SEQ)   // 4096

#define LOG2E 1.4426950408889634f

// ---------------- scratch (static device globals; no allocations) ----------
__device__ float g_qh[BATCH * NUM_HEADS * SEQ * DK];   // [B,H,S,64]
__device__ float g_kh[BATCH * NUM_HEADS * SEQ * DK];
__device__ float g_vh[BATCH * NUM_HEADS * SEQ * DK];
__device__ float g_ctx[MROWS * D_MODEL];               // [B*S, 1024]

// ---------------------------------------------------------------------------
// helpers
// ---------------------------------------------------------------------------
__device__ __forceinline__ uint32_t f2tf32(float x) {
    uint32_t u;
    asm("cvt.rna.tf32.f32 %0, %1;" : "=r"(u) : "f"(x));
    return u;
}

__device__ __forceinline__ float4 cvt4(float4 v) {
    v.x = __uint_as_float(f2tf32(v.x));
    v.y = __uint_as_float(f2tf32(v.y));
    v.z = __uint_as_float(f2tf32(v.z));
    v.w = __uint_as_float(f2tf32(v.w));
    return v;
}

// D += A(16x8) * B(8x8), tf32 inputs, fp32 accum
__device__ __forceinline__ void mma_tf32(float* c, const uint32_t* a, const uint32_t* b) {
    asm volatile(
        "mma.sync.aligned.m16n8k8.row.col.f32.tf32.tf32.f32 "
        "{%0,%1,%2,%3},{%4,%5,%6,%7},{%8,%9},{%0,%1,%2,%3};"
        : "+f"(c[0]), "+f"(c[1]), "+f"(c[2]), "+f"(c[3])
        : "r"(a[0]), "r"(a[1]), "r"(a[2]), "r"(a[3]), "r"(b[0]), "r"(b[1]));
}

// fast exp2 on the FMA pipe: x <= 0 (can be -inf). rel err ~1e-7.
__device__ __forceinline__ float fexp2(float x) {
    x = fmaxf(x, -126.0f);
    float t = x + 12582912.0f;                 // 1.5 * 2^23 (round-to-nearest int)
    int  ei = __float_as_int(t) - 0x4B400000;  // integer part
    float f = x - (t - 12582912.0f);           // frac in [-0.5, 0.5]
    float p = 1.5403530e-4f;
    p = fmaf(p, f, 1.3333558e-3f);
    p = fmaf(p, f, 9.6181291e-3f);
    p = fmaf(p, f, 5.5504109e-2f);
    p = fmaf(p, f, 2.4022650e-1f);
    p = fmaf(p, f, 6.9314718e-1f);
    p = fmaf(p, f, 1.0f);
    return p * __int_as_float((ei + 127) << 23);
}

// ---------------------------------------------------------------------------
// tf32 tensor-core GEMM: out[m,n] = (sum_k A[m,k]*W[n,k] + bias[n]) * scale
// A: [4096,1024], W: [1024,1024] row-major (row n = output feature).
// BM=BN=128, BK=16, 256 threads = 8 warps (2M x 4N), warp tile 64x32.
// ---------------------------------------------------------------------------
template <bool HEAD_LAYOUT>
__global__ __launch_bounds__(256)
void gemm_tf32_kernel(const float* __restrict__ A,
                      const float* __restrict__ W,
                      const float* __restrict__ bias,
                      float* __restrict__ out,
                      float scale)
{
    __shared__ float As[128 * 20];   // [m][k], pad to 20 -> conflict-free frags
    __shared__ float Ws[128 * 20];   // [n][k]

    const int tid  = threadIdx.x;
    const int lane = tid & 31;
    const int warp = tid >> 5;
    const int wm = warp & 1;         // 0..1
    const int wn = warp >> 1;        // 0..3
    const int g  = lane >> 2;        // 0..7
    const int c  = lane & 3;         // 0..3
    const int blockM = blockIdx.y * 128;
    const int blockN = blockIdx.x * 128;

    float acc[4][4][4];
#pragma unroll
    for (int mt = 0; mt < 4; mt++)
#pragma unroll
        for (int nt = 0; nt < 4; nt++)
#pragma unroll
            for (int r = 0; r < 4; r++) acc[mt][nt][r] = 0.f;

    for (int kt = 0; kt < D_MODEL / 16; kt++) {
        const int k0 = kt * 16;
#pragma unroll
        for (int it = 0; it < 2; it++) {
            int idx = tid + it * 256;       // 0..511
            int row = idx >> 2;             // 0..127
            int c4  = (idx & 3) * 4;        // 0,4,8,12
            float4 av = *reinterpret_cast<const float4*>(
                A + (size_t)(blockM + row) * D_MODEL + k0 + c4);
            *reinterpret_cast<float4*>(&As[row * 20 + c4]) = cvt4(av);
            float4 wv = *reinterpret_cast<const float4*>(
                W + (size_t)(blockN + row) * D_MODEL + k0 + c4);
            *reinterpret_cast<float4*>(&Ws[row * 20 + c4]) = cvt4(wv);
        }
        __syncthreads();

#pragma unroll
        for (int ks = 0; ks < 2; ks++) {
            uint32_t af[4][4], bf[4][2];
#pragma unroll
            for (int mt = 0; mt < 4; mt++) {
                const uint32_t* p = reinterpret_cast<const uint32_t*>(As)
                                  + (wm * 64 + mt * 16 + g) * 20 + ks * 8 + c;
                af[mt][0] = p[0];
                af[mt][1] = p[8 * 20];
                af[mt][2] = p[4];
                af[mt][3] = p[8 * 20 + 4];
            }
#pragma unroll
            for (int nt = 0; nt < 4; nt++) {
                const uint32_t* p = reinterpret_cast<const uint32_t*>(Ws)
                                  + (wn * 32 + nt * 8 + g) * 20 + ks * 8 + c;
                bf[nt][0] = p[0];
                bf[nt][1] = p[4];
            }
#pragma unroll
            for (int mt = 0; mt < 4; mt++)
#pragma unroll
                for (int nt = 0; nt < 4; nt++)
                    mma_tf32(acc[mt][nt], af[mt], bf[nt]);
        }
        __syncthreads();
    }

    // epilogue: rows g/g+8, col pairs 2c,2c+1
#pragma unroll
    for (int mt = 0; mt < 4; mt++) {
#pragma unroll
        for (int half = 0; half < 2; half++) {
            const int m = blockM + wm * 64 + mt * 16 + g + half * 8;
#pragma unroll
            for (int nt = 0; nt < 4; nt++) {
                const int n = blockN + wn * 32 + nt * 8 + 2 * c;
                float v0 = (acc[mt][nt][half * 2 + 0] + bias[n])     * scale;
                float v1 = (acc[mt][nt][half * 2 + 1] + bias[n + 1]) * scale;
                if (HEAD_LAYOUT) {
                    const int b = m >> 11;
                    const int s = m & 2047;
                    const int h = n >> 6;
                    const int d = n & 63;
                    float2* dst = reinterpret_cast<float2*>(
                        out + (((size_t)(b * NUM_HEADS + h) * SEQ + s) * DK) + d);
                    *dst = make_float2(v0, v1);
                } else {
                    float2* dst = reinterpret_cast<float2*>(
                        out + (size_t)m * D_MODEL + n);
                    *dst = make_float2(v0, v1);
                }
            }
        }
    }
}

// ---------------------------------------------------------------------------
// Flash attention with tf32 mma.sync. 128 q-rows per CTA, 8 warps x 16 rows.
// 64-key tiles. Q fragments live in registers for the whole loop.
// smem: Ks[64][72], Vs[64][72], Ps[128][68], maskAdd[64]  (~72 KB dynamic)
// ---------------------------------------------------------------------------
__global__ __launch_bounds__(256)
void flash_attn_tf32_kernel(const float* __restrict__ qh,
                            const float* __restrict__ kh,
                            const float* __restrict__ vh,
                            const int*   __restrict__ mask,
                            float* __restrict__ ctx)
{
    extern __shared__ float smem[];
    float* Ks = smem;                       // [64][72]
    float* Vs = Ks + 64 * 72;               // [64][72]
    float* Ps = Vs + 64 * 72;               // [128][68]
    float* mAdd = Ps + 128 * 68;            // [64]

    const int tid  = threadIdx.x;
    const int lane = tid & 31;
    const int warp = tid >> 5;              // 0..7
    const int g = lane >> 2;                // 0..7
    const int c = lane & 3;                 // 0..3
    const int b = blockIdx.z;
    const int h = blockIdx.y;
    const int q0 = blockIdx.x * 128;
    const int wrow = warp * 16;

    const float* qptr = qh + ((size_t)(b * NUM_HEADS + h) * SEQ + q0 + wrow) * DK;
    const float* kbase = kh + (size_t)(b * NUM_HEADS + h) * SEQ * DK;
    const float* vbase = vh + (size_t)(b * NUM_HEADS + h) * SEQ * DK;

    // Q fragments (A of m16n8k8): 8 k-steps x 4 regs
    uint32_t qa[8][4];
#pragma unroll
    for (int ks = 0; ks < 8; ks++) {
        qa[ks][0] = f2tf32(qptr[(g)     * DK + ks * 8 + c]);
        qa[ks][1] = f2tf32(qptr[(g + 8) * DK + ks * 8 + c]);
        qa[ks][2] = f2tf32(qptr[(g)     * DK + ks * 8 + c + 4]);
        qa[ks][3] = f2tf32(qptr[(g + 8) * DK + ks * 8 + c + 4]);
    }

    float m0 = -INFINITY, m1 = -INFINITY;
    float l0 = 0.f, l1 = 0.f;
    float o[8][4];
#pragma unroll
    for (int dt = 0; dt < 8; dt++)
#pragma unroll
        for (int r = 0; r < 4; r++) o[dt][r] = 0.f;

    for (int kt = 0; kt < SEQ / 64; kt++) {
        __syncthreads();   // protect smem from previous iteration's readers
        const float* kp = kbase + (size_t)kt * 64 * DK;
        const float* vp = vbase + (size_t)kt * 64 * DK;
#pragma unroll
        for (int it = 0; it < 4; it++) {
            int idx = tid + it * 256;        // 0..1023
            int r  = idx >> 4;               // 0..63
            int c4 = (idx & 15) * 4;         // 0..60
            float4 kv = *reinterpret_cast<const float4*>(kp + r * DK + c4);
            *reinterpret_cast<float4*>(&Ks[r * 72 + c4]) = cvt4(kv);
            float4 vv = *reinterpret_cast<const float4*>(vp + r * DK + c4);
            *reinterpret_cast<float4*>(&Vs[r * 72 + c4]) = cvt4(vv);
        }
        if (tid < 64) mAdd[tid] = (mask[b * SEQ + kt * 64 + tid] != 0) ? 0.f : -1e9f;
        __syncthreads();

        // ---- scores: S(16 x 64) = Q K^T ----
        float sc[8][4];
#pragma unroll
        for (int nt = 0; nt < 8; nt++) {
#pragma unroll
            for (int r = 0; r < 4; r++) sc[nt][r] = 0.f;
#pragma unroll
            for (int ks = 0; ks < 8; ks++) {
                uint32_t bf[2];
                const uint32_t* p = reinterpret_cast<const uint32_t*>(Ks)
                                  + (nt * 8 + g) * 72 + ks * 8 + c;
                bf[0] = p[0];
                bf[1] = p[4];
                mma_tf32(sc[nt], qa[ks], bf);
            }
            float ma0 = mAdd[nt * 8 + 2 * c];
            float ma1 = mAdd[nt * 8 + 2 * c + 1];
            sc[nt][0] += ma0; sc[nt][1] += ma1;
            sc[nt][2] += ma0; sc[nt][3] += ma1;
        }

        // ---- online softmax in C-register layout ----
        float tm0 = -INFINITY, tm1 = -INFINITY;
#pragma unroll
        for (int nt = 0; nt < 8; nt++) {
            tm0 = fmaxf(tm0, fmaxf(sc[nt][0], sc[nt][1]));
            tm1 = fmaxf(tm1, fmaxf(sc[nt][2], sc[nt][3]));
        }
        tm0 = fmaxf(tm0, __shfl_xor_sync(0xffffffffu, tm0, 1));
        tm0 = fmaxf(tm0, __shfl_xor_sync(0xffffffffu, tm0, 2));
        tm1 = fmaxf(tm1, __shfl_xor_sync(0xffffffffu, tm1, 1));
        tm1 = fmaxf(tm1, __shfl_xor_sync(0xffffffffu, tm1, 2));

        const float mn0 = fmaxf(m0, tm0);
        const float mn1 = fmaxf(m1, tm1);
        const float alpha0 = fexp2((m0 - mn0) * LOG2E);
        const float alpha1 = fexp2((m1 - mn1) * LOG2E);
        const float mn2_0 = mn0 * LOG2E;
        const float mn2_1 = mn1 * LOG2E;

        float ls0 = 0.f, ls1 = 0.f;
#pragma unroll
        for (int nt = 0; nt < 8; nt++) {
            float p0 = fexp2(fmaf(sc[nt][0], LOG2E, -mn2_0));
            float p1 = fexp2(fmaf(sc[nt][1], LOG2E, -mn2_0));
            float p2 = fexp2(fmaf(sc[nt][2], LOG2E, -mn2_1));
            float p3 = fexp2(fmaf(sc[nt][3], LOG2E, -mn2_1));
            p0 = __uint_as_float(f2tf32(p0));
            p1 = __uint_as_float(f2tf32(p1));
            p2 = __uint_as_float(f2tf32(p2));
            p3 = __uint_as_float(f2tf32(p3));
            ls0 += p0 + p1;
            ls1 += p2 + p3;
            *reinterpret_cast<float2*>(&Ps[(wrow + g)     * 68 + nt * 8 + 2 * c]) = make_float2(p0, p1);
            *reinterpret_cast<float2*>(&Ps[(wrow + g + 8) * 68 + nt * 8 + 2 * c]) = make_float2(p2, p3);
        }
        ls0 += __shfl_xor_sync(0xffffffffu, ls0, 1);
        ls0 += __shfl_xor_sync(0xffffffffu, ls0, 2);
        ls1 += __shfl_xor_sync(0xffffffffu, ls1, 1);
        ls1 += __shfl_xor_sync(0xffffffffu, ls1, 2);
        l0 = l0 * alpha0 + ls0;
        l1 = l1 * alpha1 + ls1;
        m0 = mn0;
        m1 = mn1;

#pragma unroll
        for (int dt = 0; dt < 8; dt++) {
            o[dt][0] *= alpha0; o[dt][1] *= alpha0;
            o[dt][2] *= alpha1; o[dt][3] *= alpha1;
        }
        __syncwarp();   // P visible within warp

        // ---- O += P * V ----
#pragma unroll
        for (int ks = 0; ks < 8; ks++) {
            uint32_t pa[4];
            const uint32_t* p = reinterpret_cast<const uint32_t*>(Ps)
                              + (wrow + g) * 68 + ks * 8 + c;
            pa[0] = p[0];
            pa[1] = p[8 * 68];
            pa[2] = p[4];
            pa[3] = p[8 * 68 + 4];
#pragma unroll
            for (int dt = 0; dt < 8; dt++) {
                uint32_t bf[2];
                const uint32_t* q = reinterpret_cast<const uint32_t*>(Vs)
                                  + (ks * 8 + c) * 72 + dt * 8 + g;
                bf[0] = q[0];
                bf[1] = q[4 * 72];
                mma_tf32(o[dt], pa, bf);
            }
        }
    }

    // ---- normalize + write ctx[B*S, 1024] ----
    const float r0 = 1.0f / l0;
    const float r1 = 1.0f / l1;
    float* out0 = ctx + ((size_t)(b * SEQ + q0 + wrow + g)     * D_MODEL) + h * DK;
    float* out1 = ctx + ((size_t)(b * SEQ + q0 + wrow + g + 8) * D_MODEL) + h * DK;
#pragma unroll
    for (int dt = 0; dt < 8; dt++) {
        const int col = dt * 8 + 2 * c;
        *reinterpret_cast<float2*>(out0 + col) = make_float2(o[dt][0] * r0, o[dt][1] * r0);
        *reinterpret_cast<float2*>(out1 + col) = make_float2(o[dt][2] * r1, o[dt][3] * r1);
    }
}

// ---------------------------------------------------------------------------
extern "C" void kernel_launch(void* const* d_in, const int* in_sizes, int n_in,
                              void* d_out, int out_size)
{
    const float* q    = (const float*)d_in[0];
    const float* k    = (const float*)d_in[1];
    const float* v    = (const float*)d_in[2];
    const int*   mask = (const int*)  d_in[3];
    const float* Wq   = (const float*)d_in[4];
    const float* bq   = (const float*)d_in[5];
    const float* Wk   = (const float*)d_in[6];
    const float* bk   = (const float*)d_in[7];
    const float* Wv   = (const float*)d_in[8];
    const float* bv   = (const float*)d_in[9];
    const float* Wo   = (const float*)d_in[10];
    const float* bo   = (const float*)d_in[11];
    float* out = (float*)d_out;

    float *qh, *kh, *vh, *ctx;
    cudaGetSymbolAddress((void**)&qh,  g_qh);
    cudaGetSymbolAddress((void**)&kh,  g_kh);
    cudaGetSymbolAddress((void**)&vh,  g_vh);
    cudaGetSymbolAddress((void**)&ctx, g_ctx);

    dim3 gemm_grid(D_MODEL / 128, MROWS / 128);   // (8, 32)
    const float qscale = 0.125f;                  // 1/sqrt(64)

    gemm_tf32_kernel<true><<<gemm_grid, 256>>>(q, Wq, bq, qh, qscale);
    gemm_tf32_kernel<true><<<gemm_grid, 256>>>(k, Wk, bk, kh, 1.0f);
    gemm_tf32_kernel<true><<<gemm_grid, 256>>>(v, Wv, bv, vh, 1.0f);

    size_t smem_bytes = (64 * 72 * 2 + 128 * 68 + 64) * sizeof(float);
    static bool attr_set = false;
    if (!attr_set) {
        cudaFuncSetAttribute(flash_attn_tf32_kernel,
                             cudaFuncAttributeMaxDynamicSharedMemorySize,
                             (int)smem_bytes);
        attr_set = true;
    }
    dim3 attn_grid(SEQ / 128, NUM_HEADS, BATCH);  // (16,16,2)
    flash_attn_tf32_kernel<<<attn_grid, 256, smem_bytes>>>(qh, kh, vh, mask, ctx);

    gemm_tf32_kernel<false><<<gemm_grid, 256>>>(ctx, Wo, bo, out, 1.0f);
}